// round 2
// baseline (speedup 1.0000x reference)
#include <cuda_runtime.h>
#include <math.h>

#define NN 100000
#define GG 6000
#define EE 400000
#define HH 128

// ---------------- scratch (device globals; no runtime allocation) ----------------
__device__ float g_q[(size_t)NN * HH];      // q = node_emb @ Wq + bq
__device__ float g_k[(size_t)GG * HH];      // k = group_emb @ Wk + bk
__device__ float g_val[(size_t)GG * HH];    // val = group_emb @ Wval + bval
__device__ float g_ms[(size_t)EE * HH];     // per-edge m_s
__device__ float g_msn[(size_t)NN * HH];    // scatter-added m_s per node
__device__ float g_A[(size_t)NN * HH];      // m_s_node @ L0
__device__ float g_B[(size_t)NN * HH];      // m_s_node @ L4
__device__ float g_C[(size_t)NN * HH];      // m_s_node @ L5

__device__ __forceinline__ void red_v4(float* addr, float4 v) {
    asm volatile("red.global.add.v4.f32 [%0], {%1,%2,%3,%4};"
                 :: "l"(addr), "f"(v.x), "f"(v.y), "f"(v.z), "f"(v.w) : "memory");
}

__device__ __forceinline__ float silu_f(float x) {
    return x / (1.0f + expf(-x));
}

// ---------------- generic [R,128] @ [128,128] + bias GEMM ----------------
// CTA: 64 rows x 128 cols, 256 threads. smem: W(64KB) + X tile(32KB) = 96KB.
__global__ void gemm128_bias(const float* __restrict__ X, const float* __restrict__ W,
                             const float* __restrict__ bias, float* __restrict__ Y, int R)
{
    extern __shared__ float sm[];
    float* Ws = sm;            // 128*128
    float* Xs = sm + 128 * 128; // 64*128
    const int t = threadIdx.x;
    const int r0 = blockIdx.x * 64;

    // load W (4096 float4)
    #pragma unroll
    for (int i = 0; i < 16; i++) {
        int idx = t + i * 256;
        ((float4*)Ws)[idx] = ((const float4*)W)[idx];
    }
    // load X tile (2048 float4), guard rows
    #pragma unroll
    for (int i = 0; i < 8; i++) {
        int idx = t + i * 256;       // float4 index within tile
        int row = idx >> 5;          // 32 float4 per row
        float4 v = make_float4(0.f, 0.f, 0.f, 0.f);
        if (r0 + row < R) v = ((const float4*)X)[(size_t)(r0 + row) * 32 + (idx & 31)];
        ((float4*)Xs)[idx] = v;
    }
    __syncthreads();

    const int tx = t & 31, ty = t >> 5;
    const int c4 = tx * 4;
    float acc[8][4];
    #pragma unroll
    for (int r = 0; r < 8; r++)
        #pragma unroll
        for (int c = 0; c < 4; c++) acc[r][c] = 0.f;

    #pragma unroll 4
    for (int k = 0; k < 128; k++) {
        float4 w = *(float4*)&Ws[k * 128 + c4];
        #pragma unroll
        for (int r = 0; r < 8; r++) {
            float x = Xs[(ty * 8 + r) * 128 + k];
            acc[r][0] += x * w.x; acc[r][1] += x * w.y;
            acc[r][2] += x * w.z; acc[r][3] += x * w.w;
        }
    }

    float4 b4 = make_float4(0.f, 0.f, 0.f, 0.f);
    if (bias) b4 = *(const float4*)&bias[c4];
    #pragma unroll
    for (int r = 0; r < 8; r++) {
        int row = r0 + ty * 8 + r;
        if (row < R) {
            float4 o = make_float4(acc[r][0] + b4.x, acc[r][1] + b4.y,
                                   acc[r][2] + b4.z, acc[r][3] + b4.w);
            *(float4*)&Y[(size_t)row * 128 + c4] = o;
        }
    }
}

// ---------------- per-edge attention + m_s + m_s_node scatter ----------------
// one warp per edge; lane l owns 4 channels (head = l>>2).
__global__ void edge_attn_kernel(const int* __restrict__ node_idx,
                                 const int* __restrict__ group_idx,
                                 const float* __restrict__ edge_attr)
{
    int e = (blockIdx.x * blockDim.x + threadIdx.x) >> 5;
    if (e >= EE) return;
    int lane = threadIdx.x & 31;
    int n = node_idx[e], g = group_idx[e];
    int j4 = lane * 4;

    float4 q4 = *(const float4*)&g_q[(size_t)n * 128 + j4];
    float4 k4 = *(const float4*)&g_k[(size_t)g * 128 + j4];
    float4 a4 = *(const float4*)&edge_attr[(size_t)e * 128 + j4];

    float s = q4.x * k4.x * a4.x + q4.y * k4.y * a4.y
            + q4.z * k4.z * a4.z + q4.w * k4.w * a4.w;
    // reduce within 4-lane head group
    s += __shfl_xor_sync(0xffffffffu, s, 1);
    s += __shfl_xor_sync(0xffffffffu, s, 2);
    s *= 0.25f;                 // 1/sqrt(16)
    float attn = silu_f(s);

    float4 v4 = *(const float4*)&g_val[(size_t)g * 128 + j4];
    float4 m = make_float4(v4.x * attn, v4.y * attn, v4.z * attn, v4.w * attn);
    *(float4*)&g_ms[(size_t)e * 128 + j4] = m;
    red_v4(&g_msn[(size_t)n * 128 + j4], m);
}

// ---------------- fused edge MLPs + m_v scatter (persistent) ----------------
// smem: 4 MLP weights (131KB) + biases + tiles; 32 edges per tile; 256 threads.
#define MLP_SMEM_FLOATS 49696
__global__ void edge_mlp_kernel(const int* __restrict__ node_idx,
                                const int* __restrict__ group_idx,
                                const float* __restrict__ edge_vec,
                                const float* __restrict__ group_vec,
                                const float* __restrict__ Wp1, const float* __restrict__ bp1,
                                const float* __restrict__ Wp2, const float* __restrict__ bp2,
                                const float* __restrict__ Ws1, const float* __restrict__ bs1,
                                const float* __restrict__ Ws2, const float* __restrict__ bs2,
                                float* __restrict__ dv_out)
{
    extern __shared__ float sm[];
    float* Wp1s = sm;              // 8192   [128][64]
    float* Wp2s = sm + 8192;       // 8192   [64][128]
    float* Ws1s = sm + 16384;      // 8192
    float* Ws2s = sm + 24576;      // 8192
    float* bp1s = sm + 32768;      // 64
    float* bp2s = sm + 32832;      // 128
    float* bs1s = sm + 32960;      // 64
    float* bs2s = sm + 33024;      // 128
    float* msS  = sm + 33152;      // 32*128
    float* hpS  = sm + 37248;      // 32*64
    float* hsS  = sm + 39296;      // 32*64
    float* spS  = sm + 41344;      // 32*128
    float* svS  = sm + 45440;      // 32*128
    float* uS   = sm + 49536;      // 32*3
    int*   nS   = (int*)(sm + 49632); // 32
    int*   gS   = (int*)(sm + 49664); // 32

    const int t = threadIdx.x;

    // load weights once per CTA
    {
        const float* srcs[4] = { Wp1, Wp2, Ws1, Ws2 };
        float* dsts[4] = { Wp1s, Wp2s, Ws1s, Ws2s };
        #pragma unroll
        for (int a = 0; a < 4; a++) {
            #pragma unroll
            for (int i = 0; i < 8; i++) {
                int idx = t + i * 256;   // 2048 float4
                ((float4*)dsts[a])[idx] = ((const float4*)srcs[a])[idx];
            }
        }
        if (t < 64)  bp1s[t] = bp1[t];
        if (t < 128) bp2s[t] = bp2[t];
        if (t < 64)  bs1s[t] = bs1[t];
        if (t < 128) bs2s[t] = bs2[t];
    }

    const int nTiles = (EE + 31) / 32;
    for (int tile = blockIdx.x; tile < nTiles; tile += gridDim.x) {
        const int e0 = tile * 32;
        __syncthreads();   // prior tile consumers done before overwriting smem

        // load m_s tile (1024 float4) + per-edge scalars
        #pragma unroll
        for (int i = 0; i < 4; i++) {
            int idx = t + i * 256;
            int e = e0 + (idx >> 5);
            float4 v = make_float4(0.f, 0.f, 0.f, 0.f);
            if (e < EE) v = ((const float4*)g_ms)[(size_t)e0 * 32 + idx];
            ((float4*)msS)[idx] = v;
        }
        if (t < 32) {
            int e = e0 + t;
            nS[t] = (e < EE) ? node_idx[e] : 0;
            gS[t] = (e < EE) ? group_idx[e] : 0;
        }
        if (t < 96) {
            int e = e0 + t / 3;
            uS[t] = (e < EE) ? -edge_vec[(size_t)e0 * 3 + t] : 0.f;
        }
        __syncthreads();

        // layer 1 (both MLPs): thread owns 2 rows x 4 hidden cols
        {
            const int jg = t & 15;  const int j4 = jg * 4;
            const int rg = t >> 4;  // rows rg*2, rg*2+1
            float4 ap[2], as_[2];
            ap[0] = ap[1] = as_[0] = as_[1] = make_float4(0.f, 0.f, 0.f, 0.f);
            #pragma unroll 4
            for (int k = 0; k < 128; k++) {
                float4 wp = *(float4*)&Wp1s[k * 64 + j4];
                float4 ws = *(float4*)&Ws1s[k * 64 + j4];
                #pragma unroll
                for (int r = 0; r < 2; r++) {
                    float x = msS[(rg * 2 + r) * 128 + k];
                    ap[r].x += x * wp.x; ap[r].y += x * wp.y; ap[r].z += x * wp.z; ap[r].w += x * wp.w;
                    as_[r].x += x * ws.x; as_[r].y += x * ws.y; as_[r].z += x * ws.z; as_[r].w += x * ws.w;
                }
            }
            float4 b1p = *(float4*)&bp1s[j4];
            float4 b1s = *(float4*)&bs1s[j4];
            #pragma unroll
            for (int r = 0; r < 2; r++) {
                int row = rg * 2 + r;
                float4 hp = make_float4(silu_f(ap[r].x + b1p.x), silu_f(ap[r].y + b1p.y),
                                        silu_f(ap[r].z + b1p.z), silu_f(ap[r].w + b1p.w));
                float4 hs = make_float4(silu_f(as_[r].x + b1s.x), silu_f(as_[r].y + b1s.y),
                                        silu_f(as_[r].z + b1s.z), silu_f(as_[r].w + b1s.w));
                *(float4*)&hpS[row * 64 + j4] = hp;
                *(float4*)&hsS[row * 64 + j4] = hs;
            }
        }
        __syncthreads();

        // layer 2: thread owns 4 rows x 4 out cols
        {
            const int tx = t & 31; const int c4 = tx * 4;
            const int ty = t >> 5;  // rows ty*4 .. +3
            float4 accp[4], accs[4];
            #pragma unroll
            for (int r = 0; r < 4; r++) { accp[r] = make_float4(0.f,0.f,0.f,0.f); accs[r] = make_float4(0.f,0.f,0.f,0.f); }
            #pragma unroll 4
            for (int k = 0; k < 64; k++) {
                float4 wp = *(float4*)&Wp2s[k * 128 + c4];
                float4 ws = *(float4*)&Ws2s[k * 128 + c4];
                #pragma unroll
                for (int r = 0; r < 4; r++) {
                    int row = ty * 4 + r;
                    float hp = hpS[row * 64 + k];
                    float hs = hsS[row * 64 + k];
                    accp[r].x += hp * wp.x; accp[r].y += hp * wp.y; accp[r].z += hp * wp.z; accp[r].w += hp * wp.w;
                    accs[r].x += hs * ws.x; accs[r].y += hs * ws.y; accs[r].z += hs * ws.z; accs[r].w += hs * ws.w;
                }
            }
            float4 b2p = *(float4*)&bp2s[c4];
            float4 b2s = *(float4*)&bs2s[c4];
            #pragma unroll
            for (int r = 0; r < 4; r++) {
                int row = ty * 4 + r;
                float4 sp = make_float4(accp[r].x + b2p.x, accp[r].y + b2p.y, accp[r].z + b2p.z, accp[r].w + b2p.w);
                float4 sv = make_float4(accs[r].x + b2s.x, accs[r].y + b2s.y, accs[r].z + b2s.z, accs[r].w + b2s.w);
                *(float4*)&spS[row * 128 + c4] = sp;
                *(float4*)&svS[row * 128 + c4] = sv;
            }
        }
        __syncthreads();

        // m_v = sp*u + sv*group_vec[g]; scatter into dv_out. 3072 float4 units.
        #pragma unroll
        for (int i = 0; i < 12; i++) {
            int flat = t + i * 256;
            int r = flat / 96;
            int rem = flat - r * 96;
            int d = rem >> 5;
            int c = rem & 31;
            int e = e0 + r;
            if (e < EE) {
                float4 sp = *(float4*)&spS[r * 128 + c * 4];
                float4 sv = *(float4*)&svS[r * 128 + c * 4];
                float u = uS[r * 3 + d];
                int g = gS[r];
                int n = nS[r];
                float4 gv = *(const float4*)&group_vec[((size_t)g * 3 + d) * 128 + c * 4];
                float4 mv = make_float4(sp.x * u + sv.x * gv.x, sp.y * u + sv.y * gv.y,
                                        sp.z * u + sv.z * gv.z, sp.w * u + sv.w * gv.w);
                red_v4(&dv_out[((size_t)n * 3 + d) * 128 + c * 4], mv);
            }
        }
    }
}

// ---------------- dx: (sum_d (nv@L2)*(nv@L3)) * B + C  (persistent) ----------------
__global__ void dx_kernel(const float* __restrict__ node_vec,
                          const float* __restrict__ L2w, const float* __restrict__ L3w,
                          float* __restrict__ dx_out)
{
    extern __shared__ float sm[];
    float* L2s = sm;            // 16384
    float* L3s = sm + 16384;    // 16384
    float* nvS = sm + 32768;    // 32*3*128 = 12288
    const int t = threadIdx.x;

    #pragma unroll
    for (int i = 0; i < 16; i++) {
        int idx = t + i * 256;
        ((float4*)L2s)[idx] = ((const float4*)L2w)[idx];
        ((float4*)L3s)[idx] = ((const float4*)L3w)[idx];
    }

    const int nTiles = (NN + 31) / 32;
    for (int tile = blockIdx.x; tile < nTiles; tile += gridDim.x) {
        __syncthreads();
        #pragma unroll
        for (int i = 0; i < 12; i++) {
            int idx = t + i * 256;          // float4 idx within tile (3072)
            int n = tile * 32 + idx / 96;   // 96 float4 per node
            float4 v = make_float4(0.f,0.f,0.f,0.f);
            if (n < NN) v = ((const float4*)node_vec)[(size_t)tile * 3072 + idx];
            ((float4*)nvS)[idx] = v;
        }
        __syncthreads();

        const int tx = t & 31; const int c4 = tx * 4;
        const int ty = t >> 5;   // rows ty*4..+3
        float4 s4[4];
        #pragma unroll
        for (int r = 0; r < 4; r++) s4[r] = make_float4(0.f,0.f,0.f,0.f);

        #pragma unroll
        for (int d = 0; d < 3; d++) {
            float4 a[4], b[4];
            #pragma unroll
            for (int r = 0; r < 4; r++) { a[r] = make_float4(0.f,0.f,0.f,0.f); b[r] = make_float4(0.f,0.f,0.f,0.f); }
            #pragma unroll 4
            for (int k = 0; k < 128; k++) {
                float4 w2 = *(float4*)&L2s[k * 128 + c4];
                float4 w3 = *(float4*)&L3s[k * 128 + c4];
                #pragma unroll
                for (int r = 0; r < 4; r++) {
                    float x = nvS[((ty * 4 + r) * 3 + d) * 128 + k];
                    a[r].x += x * w2.x; a[r].y += x * w2.y; a[r].z += x * w2.z; a[r].w += x * w2.w;
                    b[r].x += x * w3.x; b[r].y += x * w3.y; b[r].z += x * w3.z; b[r].w += x * w3.w;
                }
            }
            #pragma unroll
            for (int r = 0; r < 4; r++) {
                s4[r].x += a[r].x * b[r].x; s4[r].y += a[r].y * b[r].y;
                s4[r].z += a[r].z * b[r].z; s4[r].w += a[r].w * b[r].w;
            }
        }
        #pragma unroll
        for (int r = 0; r < 4; r++) {
            int n = tile * 32 + ty * 4 + r;
            if (n < NN) {
                float4 B4 = *(const float4*)&g_B[(size_t)n * 128 + c4];
                float4 C4 = *(const float4*)&g_C[(size_t)n * 128 + c4];
                float4 o = make_float4(s4[r].x * B4.x + C4.x, s4[r].y * B4.y + C4.y,
                                       s4[r].z * B4.z + C4.z, s4[r].w * B4.w + C4.w);
                *(float4*)&dx_out[(size_t)n * 128 + c4] = o;
            }
        }
    }
}

// ---------------- dv: += A * (nv @ L1)  (persistent, RMW on dv_out) ----------------
__global__ void dv_kernel(const float* __restrict__ node_vec,
                          const float* __restrict__ L1w,
                          float* __restrict__ dv_out)
{
    extern __shared__ float sm[];
    float* L1s = sm;            // 16384
    float* nvS = sm + 16384;    // 12288
    const int t = threadIdx.x;

    #pragma unroll
    for (int i = 0; i < 16; i++) {
        int idx = t + i * 256;
        ((float4*)L1s)[idx] = ((const float4*)L1w)[idx];
    }

    const int nTiles = (NN + 31) / 32;
    for (int tile = blockIdx.x; tile < nTiles; tile += gridDim.x) {
        __syncthreads();
        #pragma unroll
        for (int i = 0; i < 12; i++) {
            int idx = t + i * 256;
            int n = tile * 32 + idx / 96;
            float4 v = make_float4(0.f,0.f,0.f,0.f);
            if (n < NN) v = ((const float4*)node_vec)[(size_t)tile * 3072 + idx];
            ((float4*)nvS)[idx] = v;
        }
        __syncthreads();

        const int tx = t & 31; const int c4 = tx * 4;
        const int ty = t >> 5;
        #pragma unroll
        for (int d = 0; d < 3; d++) {
            float4 acc[4];
            #pragma unroll
            for (int r = 0; r < 4; r++) acc[r] = make_float4(0.f,0.f,0.f,0.f);
            #pragma unroll 4
            for (int k = 0; k < 128; k++) {
                float4 w = *(float4*)&L1s[k * 128 + c4];
                #pragma unroll
                for (int r = 0; r < 4; r++) {
                    float x = nvS[((ty * 4 + r) * 3 + d) * 128 + k];
                    acc[r].x += x * w.x; acc[r].y += x * w.y; acc[r].z += x * w.z; acc[r].w += x * w.w;
                }
            }
            #pragma unroll
            for (int r = 0; r < 4; r++) {
                int n = tile * 32 + ty * 4 + r;
                if (n < NN) {
                    size_t o = ((size_t)n * 3 + d) * 128 + c4;
                    float4 mv = *(float4*)&dv_out[o];
                    float4 A4 = *(const float4*)&g_A[(size_t)n * 128 + c4];
                    mv.x += A4.x * acc[r].x; mv.y += A4.y * acc[r].y;
                    mv.z += A4.z * acc[r].z; mv.w += A4.w * acc[r].w;
                    *(float4*)&dv_out[o] = mv;
                }
            }
        }
    }
}

// ---------------- launch ----------------
extern "C" void kernel_launch(void* const* d_in, const int* in_sizes, int n_in,
                              void* d_out, int out_size)
{
    const int*   node_idx        = (const int*)d_in[0];
    const int*   group_idx       = (const int*)d_in[1];
    const float* node_embedding  = (const float*)d_in[2];
    const float* node_vec        = (const float*)d_in[3];
    const float* group_embedding = (const float*)d_in[4];
    const float* group_vec       = (const float*)d_in[5];
    const float* edge_attr       = (const float*)d_in[6];
    /* d_in[7] = edge_weight (unused by reference) */
    const float* edge_vec        = (const float*)d_in[8];
    const float* Wq  = (const float*)d_in[9];  const float* bq  = (const float*)d_in[10];
    const float* Wk  = (const float*)d_in[11]; const float* bk  = (const float*)d_in[12];
    const float* Wvl = (const float*)d_in[13]; const float* bvl = (const float*)d_in[14];
    const float* Wp1 = (const float*)d_in[15]; const float* bp1 = (const float*)d_in[16];
    const float* Wp2 = (const float*)d_in[17]; const float* bp2 = (const float*)d_in[18];
    const float* Ws1 = (const float*)d_in[19]; const float* bs1 = (const float*)d_in[20];
    const float* Ws2 = (const float*)d_in[21]; const float* bs2 = (const float*)d_in[22];
    const float* L0  = (const float*)d_in[23];
    const float* L1  = (const float*)d_in[24];
    const float* L2  = (const float*)d_in[25];
    const float* L3  = (const float*)d_in[26];
    const float* L4  = (const float*)d_in[27];
    const float* L5  = (const float*)d_in[28];

    float* dx = (float*)d_out;                       // [N,128]
    float* dv = (float*)d_out + (size_t)NN * HH;     // [N,3,128]

    // smem opt-ins (idempotent; legal during capture — not stream ops)
    cudaFuncSetAttribute(gemm128_bias,   cudaFuncAttributeMaxDynamicSharedMemorySize, 98304);
    cudaFuncSetAttribute(edge_mlp_kernel,cudaFuncAttributeMaxDynamicSharedMemorySize, MLP_SMEM_FLOATS * 4);
    cudaFuncSetAttribute(dx_kernel,      cudaFuncAttributeMaxDynamicSharedMemorySize, 180224);
    cudaFuncSetAttribute(dv_kernel,      cudaFuncAttributeMaxDynamicSharedMemorySize, 114688);

    float *p_q, *p_k, *p_val, *p_msn, *p_A, *p_B, *p_C;
    cudaGetSymbolAddress((void**)&p_q,   g_q);
    cudaGetSymbolAddress((void**)&p_k,   g_k);
    cudaGetSymbolAddress((void**)&p_val, g_val);
    cudaGetSymbolAddress((void**)&p_msn, g_msn);
    cudaGetSymbolAddress((void**)&p_A,   g_A);
    cudaGetSymbolAddress((void**)&p_B,   g_B);
    cudaGetSymbolAddress((void**)&p_C,   g_C);

    cudaMemsetAsync(p_msn, 0, sizeof(float) * (size_t)NN * HH, 0);
    cudaMemsetAsync(dv,    0, sizeof(float) * (size_t)NN * 3 * HH, 0);

    gemm128_bias<<<(NN + 63) / 64, 256, 98304>>>(node_embedding,  Wq,  bq,  p_q,   NN);
    gemm128_bias<<<(GG + 63) / 64, 256, 98304>>>(group_embedding, Wk,  bk,  p_k,   GG);
    gemm128_bias<<<(GG + 63) / 64, 256, 98304>>>(group_embedding, Wvl, bvl, p_val, GG);

    edge_attn_kernel<<<(EE * 32) / 256, 256>>>(node_idx, group_idx, edge_attr);

    edge_mlp_kernel<<<148, 256, MLP_SMEM_FLOATS * 4>>>(node_idx, group_idx, edge_vec, group_vec,
                                                       Wp1, bp1, Wp2, bp2, Ws1, bs1, Ws2, bs2, dv);

    gemm128_bias<<<(NN + 63) / 64, 256, 98304>>>(p_msn, L0, nullptr, p_A, NN);
    gemm128_bias<<<(NN + 63) / 64, 256, 98304>>>(p_msn, L4, nullptr, p_B, NN);
    gemm128_bias<<<(NN + 63) / 64, 256, 98304>>>(p_msn, L5, nullptr, p_C, NN);

    dx_kernel<<<148, 256, 180224>>>(node_vec, L2, L3, dx);
    dv_kernel<<<296, 256, 114688>>>(node_vec, L1, dv);
}

// round 4
// speedup vs baseline: 1.9644x; 1.9644x over previous
#include <cuda_runtime.h>
#include <cuda_bf16.h>
#include <math.h>
#include <stdint.h>

#define NN 100000
#define GG 6000
#define EE 400000

// ---------------- scratch (device globals) ----------------
__device__ float g_q[(size_t)NN * 128];
__device__ float g_k[(size_t)GG * 128];
__device__ float g_val[(size_t)GG * 128];
__device__ float g_ms[(size_t)EE * 128];
__device__ float g_msn[(size_t)NN * 128];
__device__ float g_A[(size_t)NN * 128];
__device__ float g_B4[(size_t)NN * 128];
__device__ float g_C4[(size_t)NN * 128];
__device__ float g_hp[(size_t)EE * 64];
__device__ float g_hs[(size_t)EE * 64];
__device__ float g_sp[(size_t)EE * 128];
__device__ float g_sv[(size_t)EE * 128];
__device__ float g_v1[(size_t)NN * 384];
__device__ float g_v2[(size_t)NN * 384];
__device__ float g_t[(size_t)NN * 384];

// ---------------- helpers ----------------
__device__ __forceinline__ void red_v4(float* addr, float4 v) {
    asm volatile("red.global.add.v4.f32 [%0], {%1,%2,%3,%4};"
                 :: "l"(addr), "f"(v.x), "f"(v.y), "f"(v.z), "f"(v.w) : "memory");
}
__device__ __forceinline__ float silu_f(float x) { return x / (1.0f + expf(-x)); }

__device__ __forceinline__ uint32_t smem_u32(const void* p) {
    uint32_t a;
    asm("{ .reg .u64 t; cvta.to.shared.u64 t, %1; cvt.u32.u64 %0, t; }" : "=r"(a) : "l"(p));
    return a;
}
__device__ __forceinline__ void cpasync16(uint32_t dst, const void* src) {
    asm volatile("cp.async.cg.shared.global [%0], [%1], 16;" :: "r"(dst), "l"(src));
}
__device__ __forceinline__ void cp_commit() {
    asm volatile("cp.async.commit_group;" ::: "memory");
}
__device__ __forceinline__ void cp_wait1() {
    asm volatile("cp.async.wait_group 1;" ::: "memory");
}
__device__ __forceinline__ void cp_wait0() {
    asm volatile("cp.async.wait_group 0;" ::: "memory");
}
__device__ __forceinline__ void mma_bf16(float* d, const uint32_t* a, uint32_t b0, uint32_t b1) {
    asm volatile("mma.sync.aligned.m16n8k16.row.col.f32.bf16.bf16.f32 "
        "{%0,%1,%2,%3}, {%4,%5,%6,%7}, {%8,%9}, {%0,%1,%2,%3};"
        : "+f"(d[0]), "+f"(d[1]), "+f"(d[2]), "+f"(d[3])
        : "r"(a[0]), "r"(a[1]), "r"(a[2]), "r"(a[3]), "r"(b0), "r"(b1));
}

// ---------------- persistent bf16x3 mma.sync GEMM ----------------
// Y[R,NOUT] = X[R,KIN] @ W[KIN,NOUT] + bias  (optional silu; optional dual-W same X)
template<int KIN, int NOUT, bool SILU, bool DUAL>
__global__ void __launch_bounds__(256, 1) gemm_mma(
    const float* __restrict__ X,
    const float* __restrict__ W1, const float* __restrict__ b1, float* __restrict__ Y1,
    const float* __restrict__ W2, const float* __restrict__ b2, float* __restrict__ Y2,
    int R)
{
    constexpr int AS = KIN + 8;        // fp32 A row stride (floats)
    constexpr int KS = KIN + 8;        // bf16 B row stride (elems)
    constexpr int ND = DUAL ? 2 : 1;
    constexpr int WN = NOUT / 2;       // warp col stripe
    constexpr int NF = WN / 8;         // n-fragments per warp
    constexpr int CH = KIN / 4;        // 16B chunks per A row
    constexpr int NK = KIN / 16;

    extern __shared__ float sm[];
    float* Abuf0 = sm;
    float* Abuf1 = sm + 128 * AS;
    __nv_bfloat16* Bb = (__nv_bfloat16*)(sm + 2 * 128 * AS);
    // per weight: hi[NOUT*KS], lo[NOUT*KS]

    const int t = threadIdx.x;
    const int lane = t & 31, wid = t >> 5;
    const int wm = wid & 3, wn = wid >> 2;
    const int nT = (R + 127) >> 7;

    // ---- issue first A tile ----
    {
        int r0 = blockIdx.x << 7;
        uint32_t base = smem_u32(Abuf0);
        #pragma unroll
        for (int i = 0; i < (128 * CH) / 256; i++) {
            int idx = t + i * 256;
            int row = idx / CH, c = idx % CH;
            int gr = r0 + row; if (gr >= R) gr = R - 1;
            cpasync16(base + (uint32_t)(row * AS + c * 4) * 4, X + (size_t)gr * KIN + c * 4);
        }
        cp_commit();
    }

    // ---- load + split weights into smem (resident) ----
    #pragma unroll
    for (int w = 0; w < ND; w++) {
        const float* W = (w == 0) ? W1 : W2;
        __nv_bfloat16* BH = Bb + (size_t)w * 2 * NOUT * KS;
        __nv_bfloat16* BL = BH + NOUT * KS;
        for (int idx = t; idx < KIN * NOUT; idx += 256) {
            int k = idx / NOUT, n = idx % NOUT;
            float v = W[idx];
            __nv_bfloat16 h = __float2bfloat16(v);
            __nv_bfloat16 l = __float2bfloat16(v - __bfloat162float(h));
            BH[n * KS + k] = h;
            BL[n * KS + k] = l;
        }
    }

    int buf = 0;
    for (int tile = blockIdx.x; tile < nT; tile += gridDim.x) {
        // prefetch next tile into the other buffer
        int nt = tile + gridDim.x;
        if (nt < nT) {
            int r0 = nt << 7;
            uint32_t base = smem_u32(buf ? Abuf0 : Abuf1);
            #pragma unroll
            for (int i = 0; i < (128 * CH) / 256; i++) {
                int idx = t + i * 256;
                int row = idx / CH, c = idx % CH;
                int gr = r0 + row; if (gr >= R) gr = R - 1;
                cpasync16(base + (uint32_t)(row * AS + c * 4) * 4, X + (size_t)gr * KIN + c * 4);
            }
            cp_commit();
            cp_wait1();
        } else {
            cp_wait0();
        }
        __syncthreads();   // current A buffer (and B on first iter) visible to all

        const float* Ac = buf ? Abuf1 : Abuf0;

        float acc[ND][2][NF][4];
        #pragma unroll
        for (int w = 0; w < ND; w++)
            #pragma unroll
            for (int mf = 0; mf < 2; mf++)
                #pragma unroll
                for (int j = 0; j < NF; j++)
                    #pragma unroll
                    for (int q = 0; q < 4; q++) acc[w][mf][j][q] = 0.f;

        const int rbase = wm * 32 + (lane >> 2);
        const int klo = (lane & 3) * 2;

        #pragma unroll 2
        for (int ks = 0; ks < NK; ks++) {
            // ---- build A fragments (hi & lo) from fp32 smem ----
            uint32_t ahi[2][4], alo[2][4];
            #pragma unroll
            for (int mf = 0; mf < 2; mf++) {
                #pragma unroll
                for (int q = 0; q < 4; q++) {
                    int row = rbase + mf * 16 + (q & 1) * 8;
                    int kk = ks * 16 + klo + (q >> 1) * 8;
                    float2 v = *(const float2*)&Ac[row * AS + kk];
                    __nv_bfloat162 h = __float22bfloat162_rn(v);
                    float2 hf = __bfloat1622float2(h);
                    __nv_bfloat162 l = __float22bfloat162_rn(make_float2(v.x - hf.x, v.y - hf.y));
                    ahi[mf][q] = *(uint32_t*)&h;
                    alo[mf][q] = *(uint32_t*)&l;
                }
            }
            // ---- B fragments + 3-pass mma ----
            #pragma unroll
            for (int w = 0; w < ND; w++) {
                const __nv_bfloat16* BH = Bb + (size_t)w * 2 * NOUT * KS;
                const __nv_bfloat16* BL = BH + NOUT * KS;
                #pragma unroll
                for (int j = 0; j < NF; j++) {
                    int n = wn * WN + j * 8 + (lane >> 2);
                    int kb = ks * 16 + klo;
                    uint32_t bh0 = *(const uint32_t*)&BH[n * KS + kb];
                    uint32_t bh1 = *(const uint32_t*)&BH[n * KS + kb + 8];
                    uint32_t bl0 = *(const uint32_t*)&BL[n * KS + kb];
                    uint32_t bl1 = *(const uint32_t*)&BL[n * KS + kb + 8];
                    #pragma unroll
                    for (int mf = 0; mf < 2; mf++) {
                        mma_bf16(acc[w][mf][j], ahi[mf], bh0, bh1);
                        mma_bf16(acc[w][mf][j], ahi[mf], bl0, bl1);
                        mma_bf16(acc[w][mf][j], alo[mf], bh0, bh1);
                    }
                }
            }
        }

        // ---- epilogue ----
        int r0 = tile << 7;
        #pragma unroll
        for (int w = 0; w < ND; w++) {
            const float* bias = (w == 0) ? b1 : b2;
            float* Y = (w == 0) ? Y1 : Y2;
            #pragma unroll
            for (int mf = 0; mf < 2; mf++) {
                #pragma unroll
                for (int j = 0; j < NF; j++) {
                    int cb = wn * WN + j * 8 + (lane & 3) * 2;
                    float bx = bias ? bias[cb] : 0.f;
                    float by = bias ? bias[cb + 1] : 0.f;
                    int row = r0 + rbase + mf * 16;
                    float2 o0 = make_float2(acc[w][mf][j][0] + bx, acc[w][mf][j][1] + by);
                    float2 o1 = make_float2(acc[w][mf][j][2] + bx, acc[w][mf][j][3] + by);
                    if (SILU) {
                        o0.x = silu_f(o0.x); o0.y = silu_f(o0.y);
                        o1.x = silu_f(o1.x); o1.y = silu_f(o1.y);
                    }
                    if (row < R)     *(float2*)&Y[(size_t)row * NOUT + cb] = o0;
                    if (row + 8 < R) *(float2*)&Y[(size_t)(row + 8) * NOUT + cb] = o1;
                }
            }
        }
        __syncthreads();   // all warps done with this A buffer before it is refilled
        buf ^= 1;
    }
}

// ---------------- per-edge attention + m_s + m_s_node scatter (warp/edge) ----------------
__global__ void edge_attn_kernel(const int* __restrict__ node_idx,
                                 const int* __restrict__ group_idx,
                                 const float* __restrict__ edge_attr) {
    int e = (blockIdx.x * blockDim.x + threadIdx.x) >> 5;
    if (e >= EE) return;
    int lane = threadIdx.x & 31;
    int n = node_idx[e], g = group_idx[e];
    int j4 = lane * 4;

    float4 q4 = *(const float4*)&g_q[(size_t)n * 128 + j4];
    float4 k4 = *(const float4*)&g_k[(size_t)g * 128 + j4];
    float4 a4 = *(const float4*)&edge_attr[(size_t)e * 128 + j4];

    float s = q4.x * k4.x * a4.x + q4.y * k4.y * a4.y + q4.z * k4.z * a4.z + q4.w * k4.w * a4.w;
    s += __shfl_xor_sync(0xffffffffu, s, 1);
    s += __shfl_xor_sync(0xffffffffu, s, 2);
    s *= 0.25f;
    float attn = silu_f(s);

    float4 v4 = *(const float4*)&g_val[(size_t)g * 128 + j4];
    float4 m = make_float4(v4.x * attn, v4.y * attn, v4.z * attn, v4.w * attn);
    *(float4*)&g_ms[(size_t)e * 128 + j4] = m;
    red_v4(&g_msn[(size_t)n * 128 + j4], m);
}

// ---------------- dv prefill: dv[n,d,:] = A[n,:] * t[n,d,:] ----------------
__global__ void dv_prefill_kernel(float* __restrict__ dv) {
    size_t i = (size_t)blockIdx.x * 256 + threadIdx.x;  // float4 index over [3N,32]
    if (i >= (size_t)NN * 96) return;
    int row = (int)(i >> 5);
    int c = (int)(i & 31);
    int n = row / 3;
    float4 tt = ((const float4*)g_t)[i];
    float4 a = ((const float4*)g_A)[(size_t)n * 32 + c];
    ((float4*)dv)[i] = make_float4(a.x * tt.x, a.y * tt.y, a.z * tt.z, a.w * tt.w);
}

// ---------------- m_v scatter: dv += sp*u + sv*group_vec[g]  (warp/edge) ----------------
__global__ void mv_scatter_kernel(const int* __restrict__ node_idx,
                                  const int* __restrict__ group_idx,
                                  const float* __restrict__ edge_vec,
                                  const float* __restrict__ group_vec,
                                  float* __restrict__ dv) {
    int e = (blockIdx.x * blockDim.x + threadIdx.x) >> 5;
    if (e >= EE) return;
    int lane = threadIdx.x & 31;
    int c4 = lane * 4;
    int n = node_idx[e], g = group_idx[e];
    float4 sp = *(const float4*)&g_sp[(size_t)e * 128 + c4];
    float4 sv = *(const float4*)&g_sv[(size_t)e * 128 + c4];
    float u[3];
    u[0] = -edge_vec[(size_t)e * 3 + 0];
    u[1] = -edge_vec[(size_t)e * 3 + 1];
    u[2] = -edge_vec[(size_t)e * 3 + 2];
    #pragma unroll
    for (int d = 0; d < 3; d++) {
        float4 gv = *(const float4*)&group_vec[((size_t)g * 3 + d) * 128 + c4];
        float4 mv = make_float4(sp.x * u[d] + sv.x * gv.x, sp.y * u[d] + sv.y * gv.y,
                                sp.z * u[d] + sv.z * gv.z, sp.w * u[d] + sv.w * gv.w);
        red_v4(&dv[((size_t)n * 3 + d) * 128 + c4], mv);
    }
}

// ---------------- dx final: dx = (sum_d v1*v2) * B + C ----------------
__global__ void dx_final_kernel(float* __restrict__ dx) {
    size_t i = (size_t)blockIdx.x * 256 + threadIdx.x;  // float4 index over [N,32]
    if (i >= (size_t)NN * 32) return;
    int n = (int)(i >> 5);
    int c = (int)(i & 31);
    float4 s = make_float4(0.f, 0.f, 0.f, 0.f);
    #pragma unroll
    for (int d = 0; d < 3; d++) {
        size_t r = ((size_t)n * 3 + d) * 32 + c;
        float4 a = ((const float4*)g_v1)[r];
        float4 b = ((const float4*)g_v2)[r];
        s.x += a.x * b.x; s.y += a.y * b.y; s.z += a.z * b.z; s.w += a.w * b.w;
    }
    float4 B = ((const float4*)g_B4)[i];
    float4 C = ((const float4*)g_C4)[i];
    ((float4*)dx)[i] = make_float4(s.x * B.x + C.x, s.y * B.y + C.y,
                                   s.z * B.z + C.z, s.w * B.w + C.w);
}

// ---------------- launch ----------------
static inline int gsz(int R) { int nT = (R + 127) >> 7; return nT < 148 ? nT : 148; }

extern "C" void kernel_launch(void* const* d_in, const int* in_sizes, int n_in,
                              void* d_out, int out_size) {
    const int*   node_idx        = (const int*)d_in[0];
    const int*   group_idx       = (const int*)d_in[1];
    const float* node_embedding  = (const float*)d_in[2];
    const float* node_vec        = (const float*)d_in[3];
    const float* group_embedding = (const float*)d_in[4];
    const float* group_vec       = (const float*)d_in[5];
    const float* edge_attr       = (const float*)d_in[6];
    const float* edge_vec        = (const float*)d_in[8];
    const float* Wq  = (const float*)d_in[9];  const float* bq  = (const float*)d_in[10];
    const float* Wk  = (const float*)d_in[11]; const float* bk  = (const float*)d_in[12];
    const float* Wvl = (const float*)d_in[13]; const float* bvl = (const float*)d_in[14];
    const float* Wp1 = (const float*)d_in[15]; const float* bp1 = (const float*)d_in[16];
    const float* Wp2 = (const float*)d_in[17]; const float* bp2 = (const float*)d_in[18];
    const float* Ws1 = (const float*)d_in[19]; const float* bs1 = (const float*)d_in[20];
    const float* Ws2 = (const float*)d_in[21]; const float* bs2 = (const float*)d_in[22];
    const float* L0  = (const float*)d_in[23];
    const float* L1  = (const float*)d_in[24];
    const float* L2  = (const float*)d_in[25];
    const float* L3  = (const float*)d_in[26];
    const float* L4  = (const float*)d_in[27];
    const float* L5  = (const float*)d_in[28];

    float* dx = (float*)d_out;
    float* dv = (float*)d_out + (size_t)NN * 128;

    // smem sizes (bytes)
    const int SM_A128 = 2 * 128 * (128 + 8) * 4;            // 139264
    const int SM_A64  = 2 * 128 * (64 + 8) * 4;             //  73728
    const int SM_BIG  = SM_A128 + 128 * (128 + 8) * 4;      // 208896  <128,128,x,false>
    const int SM_DUAL = SM_A128 + 2 * 64 * (128 + 8) * 4;   // 208896  <128,64,true,true>
    const int SM_L2   = SM_A64 + 128 * (64 + 8) * 4;        // 110592  <64,128,false,false>

    cudaFuncSetAttribute(gemm_mma<128, 128, false, false>, cudaFuncAttributeMaxDynamicSharedMemorySize, SM_BIG);
    cudaFuncSetAttribute(gemm_mma<128, 64, true, true>,    cudaFuncAttributeMaxDynamicSharedMemorySize, SM_DUAL);
    cudaFuncSetAttribute(gemm_mma<64, 128, false, false>,  cudaFuncAttributeMaxDynamicSharedMemorySize, SM_L2);

    float *p_q, *p_k, *p_val, *p_ms, *p_msn, *p_A, *p_B, *p_C, *p_hp, *p_hs, *p_sp, *p_sv, *p_v1, *p_v2, *p_t;
    cudaGetSymbolAddress((void**)&p_q, g_q);     cudaGetSymbolAddress((void**)&p_k, g_k);
    cudaGetSymbolAddress((void**)&p_val, g_val); cudaGetSymbolAddress((void**)&p_ms, g_ms);
    cudaGetSymbolAddress((void**)&p_msn, g_msn); cudaGetSymbolAddress((void**)&p_A, g_A);
    cudaGetSymbolAddress((void**)&p_B, g_B4);    cudaGetSymbolAddress((void**)&p_C, g_C4);
    cudaGetSymbolAddress((void**)&p_hp, g_hp);   cudaGetSymbolAddress((void**)&p_hs, g_hs);
    cudaGetSymbolAddress((void**)&p_sp, g_sp);   cudaGetSymbolAddress((void**)&p_sv, g_sv);
    cudaGetSymbolAddress((void**)&p_v1, g_v1);   cudaGetSymbolAddress((void**)&p_v2, g_v2);
    cudaGetSymbolAddress((void**)&p_t, g_t);

    cudaMemsetAsync(p_msn, 0, sizeof(float) * (size_t)NN * 128, 0);

    // q / k / val
    gemm_mma<128, 128, false, false><<<gsz(NN), 256, SM_BIG>>>(node_embedding, Wq, bq, p_q, nullptr, nullptr, nullptr, NN);
    gemm_mma<128, 128, false, false><<<gsz(GG), 256, SM_BIG>>>(group_embedding, Wk, bk, p_k, nullptr, nullptr, nullptr, GG);
    gemm_mma<128, 128, false, false><<<gsz(GG), 256, SM_BIG>>>(group_embedding, Wvl, bvl, p_val, nullptr, nullptr, nullptr, GG);

    // attention -> m_s, m_s_node
    edge_attn_kernel<<<(EE * 32) / 256, 256>>>(node_idx, group_idx, edge_attr);

    // edge MLP layer 1 (dual: one pass over g_ms)
    gemm_mma<128, 64, true, true><<<gsz(EE), 256, SM_DUAL>>>(p_ms, Wp1, bp1, p_hp, Ws1, bs1, p_hs, EE);
    // edge MLP layer 2
    gemm_mma<64, 128, false, false><<<gsz(EE), 256, SM_L2>>>(p_hp, Wp2, bp2, p_sp, nullptr, nullptr, nullptr, EE);
    gemm_mma<64, 128, false, false><<<gsz(EE), 256, SM_L2>>>(p_hs, Ws2, bs2, p_sv, nullptr, nullptr, nullptr, EE);

    // node-side GEMMs
    gemm_mma<128, 128, false, false><<<gsz(NN), 256, SM_BIG>>>(p_msn, L0, nullptr, p_A, nullptr, nullptr, nullptr, NN);
    gemm_mma<128, 128, false, false><<<gsz(NN), 256, SM_BIG>>>(p_msn, L4, nullptr, p_B, nullptr, nullptr, nullptr, NN);
    gemm_mma<128, 128, false, false><<<gsz(NN), 256, SM_BIG>>>(p_msn, L5, nullptr, p_C, nullptr, nullptr, nullptr, NN);
    gemm_mma<128, 128, false, false><<<gsz(3 * NN), 256, SM_BIG>>>(node_vec, L1, nullptr, p_t, nullptr, nullptr, nullptr, 3 * NN);
    gemm_mma<128, 128, false, false><<<gsz(3 * NN), 256, SM_BIG>>>(node_vec, L2, nullptr, p_v1, nullptr, nullptr, nullptr, 3 * NN);
    gemm_mma<128, 128, false, false><<<gsz(3 * NN), 256, SM_BIG>>>(node_vec, L3, nullptr, p_v2, nullptr, nullptr, nullptr, 3 * NN);

    // dv = A * t, then scatter m_v on top
    dv_prefill_kernel<<<(NN * 96 + 255) / 256, 256>>>(dv);
    mv_scatter_kernel<<<(EE * 32) / 256, 256>>>(node_idx, group_idx, edge_vec, group_vec, dv);

    // dx
    dx_final_kernel<<<(NN * 32 + 255) / 256, 256>>>(dx);
}

// round 5
// speedup vs baseline: 2.0023x; 1.0193x over previous
#include <cuda_runtime.h>
#include <cuda_bf16.h>
#include <math.h>
#include <stdint.h>

#define NN 100000
#define GG 6000
#define EE 400000

// ---------------- scratch (device globals) ----------------
__device__ float g_q[(size_t)NN * 128];
__device__ float g_k[(size_t)GG * 128];
__device__ float g_val[(size_t)GG * 128];
__device__ float g_msn[(size_t)NN * 128];
__device__ float g_A[(size_t)NN * 128];
__device__ float g_B4[(size_t)NN * 128];
__device__ float g_mv[(size_t)NN * 384];

// ---------------- helpers ----------------
__device__ __forceinline__ void red_v4(float* addr, float4 v) {
    asm volatile("red.global.add.v4.f32 [%0], {%1,%2,%3,%4};"
                 :: "l"(addr), "f"(v.x), "f"(v.y), "f"(v.z), "f"(v.w) : "memory");
}
__device__ __forceinline__ void red_v2(float* addr, float x, float y) {
    asm volatile("red.global.add.v2.f32 [%0], {%1,%2};"
                 :: "l"(addr), "f"(x), "f"(y) : "memory");
}
__device__ __forceinline__ float silu_f(float x) { return x / (1.0f + expf(-x)); }

__device__ __forceinline__ uint32_t smem_u32(const void* p) {
    uint32_t a;
    asm("{ .reg .u64 t; cvta.to.shared.u64 t, %1; cvt.u32.u64 %0, t; }" : "=r"(a) : "l"(p));
    return a;
}
__device__ __forceinline__ void cpasync16(uint32_t dst, const void* src) {
    asm volatile("cp.async.cg.shared.global [%0], [%1], 16;" :: "r"(dst), "l"(src));
}
__device__ __forceinline__ void cp_commit() { asm volatile("cp.async.commit_group;" ::: "memory"); }
__device__ __forceinline__ void cp_wait1() { asm volatile("cp.async.wait_group 1;" ::: "memory"); }
__device__ __forceinline__ void cp_wait0() { asm volatile("cp.async.wait_group 0;" ::: "memory"); }

__device__ __forceinline__ void mma_bf16(float* d, const uint32_t* a, uint32_t b0, uint32_t b1) {
    asm volatile("mma.sync.aligned.m16n8k16.row.col.f32.bf16.bf16.f32 "
        "{%0,%1,%2,%3}, {%4,%5,%6,%7}, {%8,%9}, {%0,%1,%2,%3};"
        : "+f"(d[0]), "+f"(d[1]), "+f"(d[2]), "+f"(d[3])
        : "r"(a[0]), "r"(a[1]), "r"(a[2]), "r"(a[3]), "r"(b0), "r"(b1));
}

__device__ __forceinline__ void split2(float x, float y, uint32_t& h, uint32_t& l) {
    __nv_bfloat162 hh = __float22bfloat162_rn(make_float2(x, y));
    float2 hf = __bfloat1622float2(hh);
    __nv_bfloat162 ll = __float22bfloat162_rn(make_float2(x - hf.x, y - hf.y));
    h = *(uint32_t*)&hh;
    l = *(uint32_t*)&ll;
}

// ---------------- generic bf16x3 mma GEMM (KIN=128, NOUT=128, 512 thr) ----------------
// MODE 0: Y1 = X@W1 + b1
// MODE 1: Y1[row] = aux1[row] + aux2[row/3] * (X@W1)[row]            (dv combine)
// MODE 2 (DUAL): red Y1[row/3] += (X@W1)[row]*(X@W2)[row]*aux2[row/3] (dx product)
template<bool DUAL, int MODE, int DBUF>
__global__ void __launch_bounds__(512, 1) gemm_mma(
    const float* __restrict__ X,
    const float* __restrict__ W1, const float* __restrict__ b1,
    const float* __restrict__ W2,
    float* __restrict__ Y1,
    const float* __restrict__ aux1, const float* __restrict__ aux2,
    int R)
{
    constexpr int AS = 136;
    constexpr int ND = DUAL ? 2 : 1;
    extern __shared__ float sm[];
    float* Abuf0 = sm;
    float* Abuf1 = sm + (DBUF == 2 ? 128 * AS : 0);
    __nv_bfloat16* Bb = (__nv_bfloat16*)(sm + DBUF * 128 * AS);

    const int t = threadIdx.x;
    const int lane = t & 31, wid = t >> 5;
    const int wm = wid & 3, wn = wid >> 2;   // 16 warps: 4 m-stripes x 4 n-stripes(32)
    const int nT = (R + 127) >> 7;

    // first A tile
    {
        int r0 = blockIdx.x << 7;
        uint32_t base = smem_u32(Abuf0);
        #pragma unroll
        for (int i = 0; i < 8; i++) {
            int idx = t + i * 512;
            int row = idx >> 5, c = idx & 31;
            int gr = r0 + row; if (gr >= R) gr = R - 1;
            cpasync16(base + (uint32_t)(row * AS + c * 4) * 4, X + (size_t)gr * 128 + c * 4);
        }
        cp_commit();
    }

    // resident weights (hi/lo split, [n][k] col-major-for-mma)
    #pragma unroll
    for (int w = 0; w < ND; w++) {
        const float* W = (w == 0) ? W1 : W2;
        __nv_bfloat16* BH = Bb + (size_t)w * 2 * 128 * AS;
        __nv_bfloat16* BL = BH + 128 * AS;
        for (int idx = t; idx < 128 * 128; idx += 512) {
            int n = idx & 127, k = idx >> 7;
            float v = W[k * 128 + n];
            __nv_bfloat16 h = __float2bfloat16(v);
            __nv_bfloat16 l = __float2bfloat16(v - __bfloat162float(h));
            BH[n * AS + k] = h;
            BL[n * AS + k] = l;
        }
    }

    int buf = 0;
    for (int tile = blockIdx.x; tile < nT; tile += gridDim.x) {
        int nt = tile + gridDim.x;
        if (DBUF == 2) {
            if (nt < nT) {
                int r0 = nt << 7;
                uint32_t base = smem_u32(buf ? Abuf0 : Abuf1);
                #pragma unroll
                for (int i = 0; i < 8; i++) {
                    int idx = t + i * 512;
                    int row = idx >> 5, c = idx & 31;
                    int gr = r0 + row; if (gr >= R) gr = R - 1;
                    cpasync16(base + (uint32_t)(row * AS + c * 4) * 4, X + (size_t)gr * 128 + c * 4);
                }
                cp_commit(); cp_wait1();
            } else {
                cp_wait0();
            }
        } else {
            cp_wait0();
        }
        __syncthreads();

        const float* Ac = (DBUF == 2 && buf) ? Abuf1 : Abuf0;

        float acc[ND][2][4][4];
        #pragma unroll
        for (int w = 0; w < ND; w++)
            #pragma unroll
            for (int mf = 0; mf < 2; mf++)
                #pragma unroll
                for (int j = 0; j < 4; j++)
                    #pragma unroll
                    for (int q = 0; q < 4; q++) acc[w][mf][j][q] = 0.f;

        const int rb = wm * 32 + (lane >> 2);
        const int klo = (lane & 3) * 2;

        #pragma unroll
        for (int ks = 0; ks < 8; ks++) {
            uint32_t ahi[2][4], alo[2][4];
            #pragma unroll
            for (int mf = 0; mf < 2; mf++) {
                #pragma unroll
                for (int q = 0; q < 4; q++) {
                    int row = rb + mf * 16 + (q & 1) * 8;
                    int kk = ks * 16 + klo + (q >> 1) * 8;
                    float2 v = *(const float2*)&Ac[row * AS + kk];
                    __nv_bfloat162 h = __float22bfloat162_rn(v);
                    float2 hf = __bfloat1622float2(h);
                    __nv_bfloat162 l = __float22bfloat162_rn(make_float2(v.x - hf.x, v.y - hf.y));
                    ahi[mf][q] = *(uint32_t*)&h;
                    alo[mf][q] = *(uint32_t*)&l;
                }
            }
            #pragma unroll
            for (int w = 0; w < ND; w++) {
                const __nv_bfloat16* BH = Bb + (size_t)w * 2 * 128 * AS;
                const __nv_bfloat16* BL = BH + 128 * AS;
                #pragma unroll
                for (int j = 0; j < 4; j++) {
                    int n = wn * 32 + j * 8 + (lane >> 2);
                    int kb = ks * 16 + klo;
                    uint32_t bh0 = *(const uint32_t*)&BH[n * AS + kb];
                    uint32_t bh1 = *(const uint32_t*)&BH[n * AS + kb + 8];
                    uint32_t bl0 = *(const uint32_t*)&BL[n * AS + kb];
                    uint32_t bl1 = *(const uint32_t*)&BL[n * AS + kb + 8];
                    #pragma unroll
                    for (int mf = 0; mf < 2; mf++) {
                        mma_bf16(acc[w][mf][j], ahi[mf], bh0, bh1);
                        mma_bf16(acc[w][mf][j], ahi[mf], bl0, bl1);
                        mma_bf16(acc[w][mf][j], alo[mf], bh0, bh1);
                    }
                }
            }
        }

        if (DBUF == 1) {
            __syncthreads();   // all warps done reading A
            if (nt < nT) {
                int r0 = nt << 7;
                uint32_t base = smem_u32(Abuf0);
                #pragma unroll
                for (int i = 0; i < 8; i++) {
                    int idx = t + i * 512;
                    int row = idx >> 5, c = idx & 31;
                    int gr = r0 + row; if (gr >= R) gr = R - 1;
                    cpasync16(base + (uint32_t)(row * AS + c * 4) * 4, X + (size_t)gr * 128 + c * 4);
                }
                cp_commit();
            }
        }

        // ---- epilogue ----
        int r0t = tile << 7;
        #pragma unroll
        for (int mf = 0; mf < 2; mf++) {
            #pragma unroll
            for (int j = 0; j < 4; j++) {
                int cb = wn * 32 + j * 8 + (lane & 3) * 2;
                int row0 = r0t + wm * 32 + mf * 16 + (lane >> 2);
                int row1 = row0 + 8;
                if (MODE == 0) {
                    float bx = b1 ? b1[cb] : 0.f, by = b1 ? b1[cb + 1] : 0.f;
                    if (row0 < R)
                        *(float2*)&Y1[(size_t)row0 * 128 + cb] =
                            make_float2(acc[0][mf][j][0] + bx, acc[0][mf][j][1] + by);
                    if (row1 < R)
                        *(float2*)&Y1[(size_t)row1 * 128 + cb] =
                            make_float2(acc[0][mf][j][2] + bx, acc[0][mf][j][3] + by);
                } else if (MODE == 1) {
                    if (row0 < R) {
                        int n = row0 / 3;
                        float2 m = *(const float2*)&aux1[(size_t)row0 * 128 + cb];
                        float2 a = *(const float2*)&aux2[(size_t)n * 128 + cb];
                        *(float2*)&Y1[(size_t)row0 * 128 + cb] =
                            make_float2(m.x + a.x * acc[0][mf][j][0], m.y + a.y * acc[0][mf][j][1]);
                    }
                    if (row1 < R) {
                        int n = row1 / 3;
                        float2 m = *(const float2*)&aux1[(size_t)row1 * 128 + cb];
                        float2 a = *(const float2*)&aux2[(size_t)n * 128 + cb];
                        *(float2*)&Y1[(size_t)row1 * 128 + cb] =
                            make_float2(m.x + a.x * acc[0][mf][j][2], m.y + a.y * acc[0][mf][j][3]);
                    }
                } else {
                    if (row0 < R) {
                        int n = row0 / 3;
                        float2 b = *(const float2*)&aux2[(size_t)n * 128 + cb];
                        red_v2(&Y1[(size_t)n * 128 + cb],
                               acc[0][mf][j][0] * acc[1][mf][j][0] * b.x,
                               acc[0][mf][j][1] * acc[1][mf][j][1] * b.y);
                    }
                    if (row1 < R) {
                        int n = row1 / 3;
                        float2 b = *(const float2*)&aux2[(size_t)n * 128 + cb];
                        red_v2(&Y1[(size_t)n * 128 + cb],
                               acc[0][mf][j][2] * acc[1][mf][j][2] * b.x,
                               acc[0][mf][j][3] * acc[1][mf][j][3] * b.y);
                    }
                }
            }
        }
        if (DBUF == 2) { __syncthreads(); buf ^= 1; }
    }
}

// ---------------- edge megakernel ----------------
// fuses: attention (q*k*ea per head) -> m_s -> msn red -> MLP1(dual,silu) -> MLP2(dual)
//        -> m_v = sp*u + sv*gv[g] -> red into g_mv
#define ETB 512
#define MS_HI   0
#define MS_LO   17408
#define HP_HI   34816
#define HP_LO   44032
#define HS_HI   53248
#define HS_LO   62464
#define W1P_HI  71680
#define W1P_LO  89088
#define W1S_HI  106496
#define W1S_LO  123904
#define W2P_HI  141312
#define W2P_LO  159744
#define W2S_HI  178176
#define W2S_LO  196608
#define MK_NS   215040
#define MK_GS   215296
#define MK_US   215552
#define MK_BP1  216320
#define MK_BS1  216576
#define MK_BP2  216832
#define MK_BS2  217344
#define MEGA_SMEM 217856

__global__ void __launch_bounds__(ETB, 1) edge_mega(
    const int* __restrict__ node_idx, const int* __restrict__ group_idx,
    const float* __restrict__ edge_attr, const float* __restrict__ edge_vec,
    const float* __restrict__ group_vec,
    const float* __restrict__ Wp1, const float* __restrict__ bp1,
    const float* __restrict__ Wp2, const float* __restrict__ bp2,
    const float* __restrict__ Ws1, const float* __restrict__ bs1,
    const float* __restrict__ Ws2, const float* __restrict__ bs2)
{
    extern __shared__ char smc[];
    __nv_bfloat16* msHi  = (__nv_bfloat16*)(smc + MS_HI);
    __nv_bfloat16* msLo  = (__nv_bfloat16*)(smc + MS_LO);
    __nv_bfloat16* hPhi  = (__nv_bfloat16*)(smc + HP_HI);
    __nv_bfloat16* hPlo  = (__nv_bfloat16*)(smc + HP_LO);
    __nv_bfloat16* hShi  = (__nv_bfloat16*)(smc + HS_HI);
    __nv_bfloat16* hSlo  = (__nv_bfloat16*)(smc + HS_LO);
    __nv_bfloat16* w1pH  = (__nv_bfloat16*)(smc + W1P_HI);
    __nv_bfloat16* w1pL  = (__nv_bfloat16*)(smc + W1P_LO);
    __nv_bfloat16* w1sH  = (__nv_bfloat16*)(smc + W1S_HI);
    __nv_bfloat16* w1sL  = (__nv_bfloat16*)(smc + W1S_LO);
    __nv_bfloat16* w2pH  = (__nv_bfloat16*)(smc + W2P_HI);
    __nv_bfloat16* w2pL  = (__nv_bfloat16*)(smc + W2P_LO);
    __nv_bfloat16* w2sH  = (__nv_bfloat16*)(smc + W2S_HI);
    __nv_bfloat16* w2sL  = (__nv_bfloat16*)(smc + W2S_LO);
    int*   nS   = (int*)(smc + MK_NS);
    int*   gS   = (int*)(smc + MK_GS);
    float* uS   = (float*)(smc + MK_US);
    float* bp1s = (float*)(smc + MK_BP1);
    float* bs1s = (float*)(smc + MK_BS1);
    float* bp2s = (float*)(smc + MK_BP2);
    float* bs2s = (float*)(smc + MK_BS2);
    float* spS  = (float*)(smc + MS_HI);   // overlay after layer2
    float* svS  = (float*)(smc + HP_HI);   // overlay after layer2

    const int t = threadIdx.x;
    const int lane = t & 31, wid = t >> 5;
    const int wm = wid & 1, wn = wid >> 1;   // 16 warps: 2 m-stripes(32) x 8 n-stripes

    // resident weights
    for (int idx = t; idx < 64 * 128; idx += ETB) {
        int n = idx & 63, k = idx >> 6;
        float vp = Wp1[k * 64 + n], vs = Ws1[k * 64 + n];
        __nv_bfloat16 h = __float2bfloat16(vp);
        w1pH[n * 136 + k] = h;
        w1pL[n * 136 + k] = __float2bfloat16(vp - __bfloat162float(h));
        h = __float2bfloat16(vs);
        w1sH[n * 136 + k] = h;
        w1sL[n * 136 + k] = __float2bfloat16(vs - __bfloat162float(h));
    }
    for (int idx = t; idx < 128 * 64; idx += ETB) {
        int n = idx & 127, k = idx >> 7;
        float vp = Wp2[k * 128 + n], vs = Ws2[k * 128 + n];
        __nv_bfloat16 h = __float2bfloat16(vp);
        w2pH[n * 72 + k] = h;
        w2pL[n * 72 + k] = __float2bfloat16(vp - __bfloat162float(h));
        h = __float2bfloat16(vs);
        w2sH[n * 72 + k] = h;
        w2sL[n * 72 + k] = __float2bfloat16(vs - __bfloat162float(h));
    }
    if (t < 64)  { bp1s[t] = bp1[t]; bs1s[t] = bs1[t]; }
    if (t < 128) { bp2s[t] = bp2[t]; bs2s[t] = bs2[t]; }

    const int nTiles = EE / 64;
    for (int tile = blockIdx.x; tile < nTiles; tile += gridDim.x) {
        const int e0 = tile * 64;
        __syncthreads();   // staging from previous tile fully consumed

        // ---- gather + attention + m_s -> smem + msn red ----
        {
            int r = t >> 3, sub = t & 7;
            int e = e0 + r;
            int n = node_idx[e], g = group_idx[e];
            if (sub == 0) { nS[r] = n; gS[r] = g; }
            if (t < 192) uS[t] = -edge_vec[(size_t)e0 * 3 + t];
            int c0 = sub * 16;   // one head per thread (C=16)
            float s = 0.f;
            #pragma unroll
            for (int j = 0; j < 4; j++) {
                float4 q4 = *(const float4*)&g_q[(size_t)n * 128 + c0 + j * 4];
                float4 k4 = *(const float4*)&g_k[(size_t)g * 128 + c0 + j * 4];
                float4 a4 = *(const float4*)&edge_attr[(size_t)e * 128 + c0 + j * 4];
                s += q4.x * k4.x * a4.x + q4.y * k4.y * a4.y
                   + q4.z * k4.z * a4.z + q4.w * k4.w * a4.w;
            }
            float attn = silu_f(s * 0.25f);
            #pragma unroll
            for (int j = 0; j < 4; j++) {
                float4 v4 = *(const float4*)&g_val[(size_t)g * 128 + c0 + j * 4];
                float4 m = make_float4(v4.x * attn, v4.y * attn, v4.z * attn, v4.w * attn);
                red_v4(&g_msn[(size_t)n * 128 + c0 + j * 4], m);
                uint32_t h0, l0, h1, l1;
                split2(m.x, m.y, h0, l0);
                split2(m.z, m.w, h1, l1);
                int bidx = r * 136 + c0 + j * 4;
                *(uint32_t*)&msHi[bidx] = h0;     *(uint32_t*)&msHi[bidx + 2] = h1;
                *(uint32_t*)&msLo[bidx] = l0;     *(uint32_t*)&msLo[bidx + 2] = l1;
            }
        }
        __syncthreads();

        // ---- layer 1: [64,128]@[128,64] dual, silu -> h ----
        {
            float accP[2][4], accS[2][4];
            #pragma unroll
            for (int mf = 0; mf < 2; mf++)
                #pragma unroll
                for (int q = 0; q < 4; q++) { accP[mf][q] = 0.f; accS[mf][q] = 0.f; }
            const int rB = wm * 32 + (lane >> 2);
            const int klo = (lane & 3) * 2;
            #pragma unroll
            for (int ks = 0; ks < 8; ks++) {
                uint32_t ahi[2][4], alo[2][4];
                #pragma unroll
                for (int mf = 0; mf < 2; mf++)
                    #pragma unroll
                    for (int q = 0; q < 4; q++) {
                        int row = rB + mf * 16 + (q & 1) * 8;
                        int kk = ks * 16 + klo + (q >> 1) * 8;
                        ahi[mf][q] = *(const uint32_t*)&msHi[row * 136 + kk];
                        alo[mf][q] = *(const uint32_t*)&msLo[row * 136 + kk];
                    }
                int nIdx = wn * 8 + (lane >> 2);
                int kb = ks * 16 + klo;
                uint32_t ph0 = *(const uint32_t*)&w1pH[nIdx * 136 + kb];
                uint32_t ph1 = *(const uint32_t*)&w1pH[nIdx * 136 + kb + 8];
                uint32_t pl0 = *(const uint32_t*)&w1pL[nIdx * 136 + kb];
                uint32_t pl1 = *(const uint32_t*)&w1pL[nIdx * 136 + kb + 8];
                uint32_t sh0 = *(const uint32_t*)&w1sH[nIdx * 136 + kb];
                uint32_t sh1 = *(const uint32_t*)&w1sH[nIdx * 136 + kb + 8];
                uint32_t sl0 = *(const uint32_t*)&w1sL[nIdx * 136 + kb];
                uint32_t sl1 = *(const uint32_t*)&w1sL[nIdx * 136 + kb + 8];
                #pragma unroll
                for (int mf = 0; mf < 2; mf++) {
                    mma_bf16(accP[mf], ahi[mf], ph0, ph1);
                    mma_bf16(accP[mf], ahi[mf], pl0, pl1);
                    mma_bf16(accP[mf], alo[mf], ph0, ph1);
                    mma_bf16(accS[mf], ahi[mf], sh0, sh1);
                    mma_bf16(accS[mf], ahi[mf], sl0, sl1);
                    mma_bf16(accS[mf], alo[mf], sh0, sh1);
                }
            }
            int cb = wn * 8 + (lane & 3) * 2;
            float b0p = bp1s[cb], b1p = bp1s[cb + 1];
            float b0s = bs1s[cb], b1s = bs1s[cb + 1];
            #pragma unroll
            for (int mf = 0; mf < 2; mf++) {
                int row = wm * 32 + mf * 16 + (lane >> 2);
                uint32_t h, l;
                split2(silu_f(accP[mf][0] + b0p), silu_f(accP[mf][1] + b1p), h, l);
                *(uint32_t*)&hPhi[row * 72 + cb] = h;  *(uint32_t*)&hPlo[row * 72 + cb] = l;
                split2(silu_f(accP[mf][2] + b0p), silu_f(accP[mf][3] + b1p), h, l);
                *(uint32_t*)&hPhi[(row + 8) * 72 + cb] = h;  *(uint32_t*)&hPlo[(row + 8) * 72 + cb] = l;
                split2(silu_f(accS[mf][0] + b0s), silu_f(accS[mf][1] + b1s), h, l);
                *(uint32_t*)&hShi[row * 72 + cb] = h;  *(uint32_t*)&hSlo[row * 72 + cb] = l;
                split2(silu_f(accS[mf][2] + b0s), silu_f(accS[mf][3] + b1s), h, l);
                *(uint32_t*)&hShi[(row + 8) * 72 + cb] = h;  *(uint32_t*)&hSlo[(row + 8) * 72 + cb] = l;
            }
        }
        __syncthreads();

        // ---- layer 2: [64,64]@[64,128] dual ----
        float acc2P[2][2][4], acc2S[2][2][4];
        #pragma unroll
        for (int mf = 0; mf < 2; mf++)
            #pragma unroll
            for (int j = 0; j < 2; j++)
                #pragma unroll
                for (int q = 0; q < 4; q++) { acc2P[mf][j][q] = 0.f; acc2S[mf][j][q] = 0.f; }
        {
            const int rB = wm * 32 + (lane >> 2);
            const int klo = (lane & 3) * 2;
            #pragma unroll
            for (int ks = 0; ks < 4; ks++) {
                uint32_t aPh[2][4], aPl[2][4], aSh[2][4], aSl[2][4];
                #pragma unroll
                for (int mf = 0; mf < 2; mf++)
                    #pragma unroll
                    for (int q = 0; q < 4; q++) {
                        int row = rB + mf * 16 + (q & 1) * 8;
                        int kk = ks * 16 + klo + (q >> 1) * 8;
                        int off = row * 72 + kk;
                        aPh[mf][q] = *(const uint32_t*)&hPhi[off];
                        aPl[mf][q] = *(const uint32_t*)&hPlo[off];
                        aSh[mf][q] = *(const uint32_t*)&hShi[off];
                        aSl[mf][q] = *(const uint32_t*)&hSlo[off];
                    }
                #pragma unroll
                for (int j = 0; j < 2; j++) {
                    int nIdx = wn * 16 + j * 8 + (lane >> 2);
                    int kb = ks * 16 + klo;
                    uint32_t ph0 = *(const uint32_t*)&w2pH[nIdx * 72 + kb];
                    uint32_t ph1 = *(const uint32_t*)&w2pH[nIdx * 72 + kb + 8];
                    uint32_t pl0 = *(const uint32_t*)&w2pL[nIdx * 72 + kb];
                    uint32_t pl1 = *(const uint32_t*)&w2pL[nIdx * 72 + kb + 8];
                    uint32_t sh0 = *(const uint32_t*)&w2sH[nIdx * 72 + kb];
                    uint32_t sh1 = *(const uint32_t*)&w2sH[nIdx * 72 + kb + 8];
                    uint32_t sl0 = *(const uint32_t*)&w2sL[nIdx * 72 + kb];
                    uint32_t sl1 = *(const uint32_t*)&w2sL[nIdx * 72 + kb + 8];
                    #pragma unroll
                    for (int mf = 0; mf < 2; mf++) {
                        mma_bf16(acc2P[mf][j], aPh[mf], ph0, ph1);
                        mma_bf16(acc2P[mf][j], aPh[mf], pl0, pl1);
                        mma_bf16(acc2P[mf][j], aPl[mf], ph0, ph1);
                        mma_bf16(acc2S[mf][j], aSh[mf], sh0, sh1);
                        mma_bf16(acc2S[mf][j], aSh[mf], sl0, sl1);
                        mma_bf16(acc2S[mf][j], aSl[mf], sh0, sh1);
                    }
                }
            }
        }
        __syncthreads();   // all h/ms reads done before staging overwrites

        // ---- stage sp/sv to smem ----
        #pragma unroll
        for (int mf = 0; mf < 2; mf++) {
            #pragma unroll
            for (int j = 0; j < 2; j++) {
                int row = wm * 32 + mf * 16 + (lane >> 2);
                int cb = wn * 16 + j * 8 + (lane & 3) * 2;
                float b0p = bp2s[cb], b1p = bp2s[cb + 1];
                float b0s = bs2s[cb], b1s = bs2s[cb + 1];
                *(float2*)&spS[row * 132 + cb] =
                    make_float2(acc2P[mf][j][0] + b0p, acc2P[mf][j][1] + b1p);
                *(float2*)&spS[(row + 8) * 132 + cb] =
                    make_float2(acc2P[mf][j][2] + b0p, acc2P[mf][j][3] + b1p);
                *(float2*)&svS[row * 132 + cb] =
                    make_float2(acc2S[mf][j][0] + b0s, acc2S[mf][j][1] + b1s);
                *(float2*)&svS[(row + 8) * 132 + cb] =
                    make_float2(acc2S[mf][j][2] + b0s, acc2S[mf][j][3] + b1s);
            }
        }
        __syncthreads();

        // ---- m_v scatter: g_mv[n,d,:] += sp*u[d] + sv*gv[g,d,:] ----
        #pragma unroll
        for (int i = 0; i < 12; i++) {
            int flat = t + i * ETB;        // 64*96 = 6144 float4 units
            int r = flat / 96;
            int rem = flat - r * 96;
            int d = rem >> 5, c = rem & 31;
            float4 sp = *(float4*)&spS[r * 132 + c * 4];
            float4 sv = *(float4*)&svS[r * 132 + c * 4];
            float u = uS[r * 3 + d];
            int gg = gS[r], nn = nS[r];
            float4 gv = *(const float4*)&group_vec[((size_t)gg * 3 + d) * 128 + c * 4];
            float4 mv = make_float4(sp.x * u + sv.x * gv.x, sp.y * u + sv.y * gv.y,
                                    sp.z * u + sv.z * gv.z, sp.w * u + sv.w * gv.w);
            red_v4(&g_mv[((size_t)nn * 3 + d) * 128 + c * 4], mv);
        }
    }
}

// ---------------- launch ----------------
static inline int gsz(int R) { int nT = (R + 127) >> 7; return nT < 148 ? nT : 148; }

extern "C" void kernel_launch(void* const* d_in, const int* in_sizes, int n_in,
                              void* d_out, int out_size) {
    const int*   node_idx        = (const int*)d_in[0];
    const int*   group_idx       = (const int*)d_in[1];
    const float* node_embedding  = (const float*)d_in[2];
    const float* node_vec        = (const float*)d_in[3];
    const float* group_embedding = (const float*)d_in[4];
    const float* group_vec       = (const float*)d_in[5];
    const float* edge_attr       = (const float*)d_in[6];
    const float* edge_vec        = (const float*)d_in[8];
    const float* Wq  = (const float*)d_in[9];  const float* bq  = (const float*)d_in[10];
    const float* Wk  = (const float*)d_in[11]; const float* bk  = (const float*)d_in[12];
    const float* Wvl = (const float*)d_in[13]; const float* bvl = (const float*)d_in[14];
    const float* Wp1 = (const float*)d_in[15]; const float* bp1 = (const float*)d_in[16];
    const float* Wp2 = (const float*)d_in[17]; const float* bp2 = (const float*)d_in[18];
    const float* Ws1 = (const float*)d_in[19]; const float* bs1 = (const float*)d_in[20];
    const float* Ws2 = (const float*)d_in[21]; const float* bs2 = (const float*)d_in[22];
    const float* L0  = (const float*)d_in[23];
    const float* L1  = (const float*)d_in[24];
    const float* L2  = (const float*)d_in[25];
    const float* L3  = (const float*)d_in[26];
    const float* L4  = (const float*)d_in[27];
    const float* L5  = (const float*)d_in[28];

    float* dx = (float*)d_out;
    float* dv = (float*)d_out + (size_t)NN * 128;

    const int SM_G = 208896;
    cudaFuncSetAttribute(gemm_mma<false, 0, 2>, cudaFuncAttributeMaxDynamicSharedMemorySize, SM_G);
    cudaFuncSetAttribute(gemm_mma<false, 1, 2>, cudaFuncAttributeMaxDynamicSharedMemorySize, SM_G);
    cudaFuncSetAttribute(gemm_mma<true, 2, 1>,  cudaFuncAttributeMaxDynamicSharedMemorySize, SM_G);
    cudaFuncSetAttribute(edge_mega, cudaFuncAttributeMaxDynamicSharedMemorySize, MEGA_SMEM);

    float *p_q, *p_k, *p_val, *p_msn, *p_A, *p_B, *p_mv;
    cudaGetSymbolAddress((void**)&p_q, g_q);
    cudaGetSymbolAddress((void**)&p_k, g_k);
    cudaGetSymbolAddress((void**)&p_val, g_val);
    cudaGetSymbolAddress((void**)&p_msn, g_msn);
    cudaGetSymbolAddress((void**)&p_A, g_A);
    cudaGetSymbolAddress((void**)&p_B, g_B4);
    cudaGetSymbolAddress((void**)&p_mv, g_mv);

    cudaMemsetAsync(p_msn, 0, sizeof(float) * (size_t)NN * 128, 0);
    cudaMemsetAsync(p_mv,  0, sizeof(float) * (size_t)NN * 384, 0);

    // q / k / val
    gemm_mma<false, 0, 2><<<gsz(NN), 512, SM_G>>>(node_embedding, Wq, bq, nullptr, p_q, nullptr, nullptr, NN);
    gemm_mma<false, 0, 2><<<gsz(GG), 512, SM_G>>>(group_embedding, Wk, bk, nullptr, p_k, nullptr, nullptr, GG);
    gemm_mma<false, 0, 2><<<gsz(GG), 512, SM_G>>>(group_embedding, Wvl, bvl, nullptr, p_val, nullptr, nullptr, GG);

    // fused edge pipeline
    edge_mega<<<148, ETB, MEGA_SMEM>>>(node_idx, group_idx, edge_attr, edge_vec, group_vec,
                                       Wp1, bp1, Wp2, bp2, Ws1, bs1, Ws2, bs2);

    // node-side: A = msn@L0, B = msn@L4, dx = msn@L5 (C)
    gemm_mma<false, 0, 2><<<gsz(NN), 512, SM_G>>>(p_msn, L0, nullptr, nullptr, p_A, nullptr, nullptr, NN);
    gemm_mma<false, 0, 2><<<gsz(NN), 512, SM_G>>>(p_msn, L4, nullptr, nullptr, p_B, nullptr, nullptr, NN);
    gemm_mma<false, 0, 2><<<gsz(NN), 512, SM_G>>>(p_msn, L5, nullptr, nullptr, dx, nullptr, nullptr, NN);

    // dv = g_mv + A[n] * (nv@L1)
    gemm_mma<false, 1, 2><<<gsz(3 * NN), 512, SM_G>>>(node_vec, L1, nullptr, nullptr, dv, p_mv, p_A, 3 * NN);

    // dx += sum_d (nv@L2)*(nv@L3)*B[n]   (red onto dx = C)
    gemm_mma<true, 2, 1><<<gsz(3 * NN), 512, SM_G>>>(node_vec, L2, nullptr, L3, dx, nullptr, p_B, 3 * NN);
}